// round 1
// baseline (speedup 1.0000x reference)
#include <cuda_runtime.h>
#include <cuda_bf16.h>
#include <cstdint>

// Problem shape (fixed): x (2,2048,4096) fp32, weight (4096,4096) fp32 (pre-quantized
// per-channel), bias (4096) fp32, had_dim = 64. Output (2,2048,4096) fp32.
#define M_DIM 4096   // B*S tokens
#define N_DIM 4096   // D_OUT
#define K_DIM 4096   // D_IN

// ---------------- scratch (static __device__; no runtime alloc) ----------------
__device__ __nv_bfloat16 g_qx[(size_t)M_DIM * K_DIM];  // quantized activations (int values in bf16)
__device__ __nv_bfloat16 g_qw[(size_t)N_DIM * K_DIM];  // quantized weights (int values in bf16)
__device__ float g_st[M_DIM];                          // per-token scale
__device__ float g_so[N_DIM];                          // per-channel scale

// ---------------- kernel 1: recover int8 weight + per-channel scale ----------------
__global__ __launch_bounds__(256) void quant_weight_kernel(const float* __restrict__ w) {
    __shared__ float s[K_DIM];
    __shared__ float red[8];
    const int o = blockIdx.x;
    const float* wr = w + (size_t)o * K_DIM;

    float m = 0.f;
    for (int i = threadIdx.x; i < K_DIM; i += 256) {
        float v = wr[i];
        s[i] = v;
        m = fmaxf(m, fabsf(v));
    }
    #pragma unroll
    for (int off = 16; off > 0; off >>= 1)
        m = fmaxf(m, __shfl_xor_sync(0xffffffffu, m, off));
    if ((threadIdx.x & 31) == 0) red[threadIdx.x >> 5] = m;
    __syncthreads();
    m = red[0];
    #pragma unroll
    for (int i = 1; i < 8; i++) m = fmaxf(m, red[i]);

    const float scale = fmaxf(m / 127.0f, 1e-5f);
    const float inv = 1.0f / scale;
    if (threadIdx.x == 0) g_so[o] = scale;

    __nv_bfloat16* qr = g_qw + (size_t)o * K_DIM;
    for (int i = threadIdx.x; i < K_DIM; i += 256)
        qr[i] = __float2bfloat16(rintf(s[i] * inv));  // exact integer recovery
}

// ---------------- kernel 2: partial Hadamard (FWHT over group axis) + per-token quant ----------------
__global__ __launch_bounds__(256) void had_quant_kernel(const float* __restrict__ x) {
    __shared__ float s[K_DIM];
    __shared__ float red[8];
    const int t = blockIdx.x;  // token
    const float* xr = x + (size_t)t * K_DIM;

    for (int i = threadIdx.x; i < K_DIM; i += 256) s[i] = xr[i];
    __syncthreads();

    // FWHT over the group index g (flat index bits 6..11), Sylvester order.
    #pragma unroll
    for (int st = 0; st < 6; st++) {
        const int h = 64 << st;            // pair distance in flat index
        const int lb = 6 + st;             // bit being butterflied
        const int lmask = (1 << lb) - 1;
        for (int p = threadIdx.x; p < 2048; p += 256) {
            int i = ((p >> lb) << (lb + 1)) | (p & lmask);
            float a = s[i], b = s[i + h];
            s[i] = a + b;
            s[i + h] = a - b;
        }
        __syncthreads();
    }

    // absmax of y = s * 0.125
    float m = 0.f;
    for (int i = threadIdx.x; i < K_DIM; i += 256) m = fmaxf(m, fabsf(s[i]));
    #pragma unroll
    for (int off = 16; off > 0; off >>= 1)
        m = fmaxf(m, __shfl_xor_sync(0xffffffffu, m, off));
    if ((threadIdx.x & 31) == 0) red[threadIdx.x >> 5] = m;
    __syncthreads();
    m = red[0];
    #pragma unroll
    for (int i = 1; i < 8; i++) m = fmaxf(m, red[i]);

    const float amax = 0.125f * m;                       // exact (power-of-two scale)
    const float scale = fmaxf(amax / 127.0f, 1e-5f);
    const float inv = 1.0f / scale;
    if (threadIdx.x == 0) g_st[t] = scale;

    __nv_bfloat16* qr = g_qx + (size_t)t * K_DIM;
    for (int i = threadIdx.x; i < K_DIM; i += 256)
        qr[i] = __float2bfloat16(rintf((s[i] * 0.125f) * inv));
}

// ---------------- kernel 3: bf16 tensor-core GEMM (integer-exact), fused scale+bias ----------------
// out[m][n] = s_t[m]*s_o[n] * sum_k q_x[m][k]*q_w[n][k] + bias[n]
#define BM 128
#define BN 128
#define BK 32
#define PAD 8

__device__ __forceinline__ void mma16816(float d[4], const uint32_t a[4], const uint32_t b[2]) {
    asm volatile(
        "mma.sync.aligned.m16n8k16.row.col.f32.bf16.bf16.f32 "
        "{%0,%1,%2,%3}, {%4,%5,%6,%7}, {%8,%9}, {%0,%1,%2,%3};\n"
        : "+f"(d[0]), "+f"(d[1]), "+f"(d[2]), "+f"(d[3])
        : "r"(a[0]), "r"(a[1]), "r"(a[2]), "r"(a[3]), "r"(b[0]), "r"(b[1]));
}

__global__ __launch_bounds__(256) void gemm_kernel(float* __restrict__ out,
                                                   const float* __restrict__ bias) {
    __shared__ __nv_bfloat16 As[BM][BK + PAD];
    __shared__ __nv_bfloat16 Bs[BN][BK + PAD];

    const int bm = blockIdx.y, bn = blockIdx.x;
    const int tid = threadIdx.x;
    const int wid = tid >> 5, lane = tid & 31;
    const int wm = wid >> 2;       // 0..1  -> 64 rows each
    const int wn = wid & 3;        // 0..3  -> 32 cols each
    const int grp = lane >> 2;     // groupID (0..7)
    const int tig = lane & 3;      // thread in group

    float acc[4][4][4];
    #pragma unroll
    for (int i = 0; i < 4; i++)
        #pragma unroll
        for (int j = 0; j < 4; j++)
            #pragma unroll
            for (int r = 0; r < 4; r++) acc[i][j][r] = 0.f;

    const __nv_bfloat16* Ag = g_qx + (size_t)(bm * BM) * K_DIM;
    const __nv_bfloat16* Bg = g_qw + (size_t)(bn * BN) * K_DIM;

    // loader: each 16B chunk = 8 bf16; row = 4 chunks; 256 thr * 2 passes covers 128 rows
    const int lr = tid >> 2;        // 0..63
    const int lc = tid & 3;         // chunk in row

    for (int kt = 0; kt < K_DIM; kt += BK) {
        #pragma unroll
        for (int p = 0; p < 2; p++) {
            const int r = lr + p * 64;
            *(uint4*)&As[r][lc * 8] = *(const uint4*)&Ag[(size_t)r * K_DIM + kt + lc * 8];
            *(uint4*)&Bs[r][lc * 8] = *(const uint4*)&Bg[(size_t)r * K_DIM + kt + lc * 8];
        }
        __syncthreads();

        #pragma unroll
        for (int ks = 0; ks < 2; ks++) {
            const int k0 = ks * 16;
            uint32_t a[4][4];
            uint32_t b[4][2];
            #pragma unroll
            for (int mt = 0; mt < 4; mt++) {
                const int row = wm * 64 + mt * 16 + grp;
                const int col = k0 + tig * 2;
                a[mt][0] = *(const uint32_t*)&As[row][col];
                a[mt][1] = *(const uint32_t*)&As[row + 8][col];
                a[mt][2] = *(const uint32_t*)&As[row][col + 8];
                a[mt][3] = *(const uint32_t*)&As[row + 8][col + 8];
            }
            #pragma unroll
            for (int nt = 0; nt < 4; nt++) {
                const int nb = wn * 32 + nt * 8 + grp;
                const int col = k0 + tig * 2;
                b[nt][0] = *(const uint32_t*)&Bs[nb][col];
                b[nt][1] = *(const uint32_t*)&Bs[nb][col + 8];
            }
            #pragma unroll
            for (int mt = 0; mt < 4; mt++)
                #pragma unroll
                for (int nt = 0; nt < 4; nt++)
                    mma16816(acc[mt][nt], a[mt], b[nt]);
        }
        __syncthreads();
    }

    // epilogue: out = s_t*s_o*acc + bias
    #pragma unroll
    for (int mt = 0; mt < 4; mt++) {
        const int mrow = bm * BM + wm * 64 + mt * 16 + grp;
        const float st0 = g_st[mrow];
        const float st1 = g_st[mrow + 8];
        #pragma unroll
        for (int nt = 0; nt < 4; nt++) {
            const int ncol = bn * BN + wn * 32 + nt * 8 + tig * 2;
            const float so0 = g_so[ncol], so1 = g_so[ncol + 1];
            const float bi0 = bias[ncol], bi1 = bias[ncol + 1];
            float2 v0, v1;
            v0.x = fmaf(st0 * so0, acc[mt][nt][0], bi0);
            v0.y = fmaf(st0 * so1, acc[mt][nt][1], bi1);
            v1.x = fmaf(st1 * so0, acc[mt][nt][2], bi0);
            v1.y = fmaf(st1 * so1, acc[mt][nt][3], bi1);
            *(float2*)&out[(size_t)mrow * N_DIM + ncol] = v0;
            *(float2*)&out[(size_t)(mrow + 8) * N_DIM + ncol] = v1;
        }
    }
}

// ---------------- launcher ----------------
extern "C" void kernel_launch(void* const* d_in, const int* in_sizes, int n_in,
                              void* d_out, int out_size) {
    const float* x = (const float*)d_in[0];
    const float* w = (const float*)d_in[1];
    const float* bias = (const float*)d_in[2];
    float* out = (float*)d_out;
    (void)in_sizes; (void)n_in; (void)out_size;

    quant_weight_kernel<<<N_DIM, 256>>>(w);
    had_quant_kernel<<<M_DIM, 256>>>(x);
    dim3 grid(N_DIM / BN, M_DIM / BM);
    gemm_kernel<<<grid, 256>>>(out, bias);
}